// round 1
// baseline (speedup 1.0000x reference)
#include <cuda_runtime.h>
#include <cstdint>

// Problem constants (fixed shapes per reference)
#define NMAX 100000
#define EMAX 1600000
#define HDIM 128
#define G3   384   // 3 * HG

// ---------------- scratch (device globals; allocation-free) ----------------
__device__ float g_xh[(size_t)NMAX * HDIM];
__device__ float g_xw[(size_t)NMAX * HDIM];
__device__ float g_agg[(size_t)NMAX * HDIM];
__device__ float g_h[(size_t)NMAX * HDIM];
__device__ float g_gi[(size_t)NMAX * G3];
__device__ float g_gh[(size_t)NMAX * G3];
__device__ float g_deg[NMAX];
__device__ float g_dinv[NMAX];
__device__ float g_norm[EMAX];
__device__ float g_WihT[HDIM * G3];
__device__ float g_WhhT[HDIM * G3];

// ---------------- small utility kernels ----------------

__global__ void transpose_g_kernel(const float* __restrict__ W, float* __restrict__ WT,
                                   int rows, int cols) {
    // WT[c][r] = W[r][c];  W is [rows, cols]
    int idx = blockIdx.x * blockDim.x + threadIdx.x;
    if (idx < rows * cols) {
        int r = idx / cols, c = idx % cols;
        WT[c * rows + r] = W[idx];
    }
}

__global__ void init_deg_kernel(float* __restrict__ deg, int n) {
    int i = blockIdx.x * blockDim.x + threadIdx.x;
    if (i < n) deg[i] = 1.0f;  // self-loop weight 1
}

__global__ void deg_accum_kernel(const int* __restrict__ dst, const float* __restrict__ ew,
                                 float* __restrict__ deg, int E) {
    int e = blockIdx.x * blockDim.x + threadIdx.x;
    if (e < E) atomicAdd(&deg[dst[e]], ew[e]);
}

__global__ void dinv_kernel(const float* __restrict__ deg, float* __restrict__ dinv, int n) {
    int i = blockIdx.x * blockDim.x + threadIdx.x;
    if (i < n) {
        float d = deg[i];
        dinv[i] = (d > 0.0f) ? rsqrtf(d) : 0.0f;
    }
}

__global__ void norm_kernel(const int* __restrict__ src, const int* __restrict__ dst,
                            const float* __restrict__ ew, const float* __restrict__ dinv,
                            float* __restrict__ norm, int E) {
    int e = blockIdx.x * blockDim.x + threadIdx.x;
    if (e < E) norm[e] = dinv[src[e]] * ew[e] * dinv[dst[e]];
}

__global__ void zero_kernel(float* __restrict__ p, size_t n) {
    size_t i = (size_t)blockIdx.x * blockDim.x + threadIdx.x;
    size_t stride = (size_t)gridDim.x * blockDim.x;
    for (; i < n; i += stride) p[i] = 0.0f;
}

// ---------------- SGEMM: C[M,Nc] = A[M,128] @ B[128,Nc] (+bias)(+relu) ----------------
// BM=BN=BK=64, 256 threads, 4x4 microtile per thread.
template <int ACT>
__global__ __launch_bounds__(256) void sgemm_k128(
    const float* __restrict__ A, const float* __restrict__ B,
    const float* __restrict__ bias, float* __restrict__ C, int M, int Nc)
{
    __shared__ float As[64][68];
    __shared__ float Bs[64][68];
    const int tid = threadIdx.x;
    const int tx = tid & 15;
    const int ty = tid >> 4;
    const int m0 = blockIdx.y << 6;
    const int n0 = blockIdx.x << 6;

    float acc[4][4];
#pragma unroll
    for (int m = 0; m < 4; m++)
#pragma unroll
        for (int n = 0; n < 4; n++) acc[m][n] = 0.0f;

    for (int k0 = 0; k0 < 128; k0 += 64) {
#pragma unroll
        for (int i = 0; i < 4; i++) {
            int idx = tid + (i << 8);
            int r = idx >> 4;
            int c = (idx & 15) << 2;
            float4 v = make_float4(0.f, 0.f, 0.f, 0.f);
            int gr = m0 + r;
            if (gr < M) v = *(const float4*)(A + (size_t)gr * 128 + k0 + c);
            *(float4*)&As[r][c] = v;
        }
#pragma unroll
        for (int i = 0; i < 4; i++) {
            int idx = tid + (i << 8);
            int r = idx >> 4;
            int c = (idx & 15) << 2;
            float4 v = make_float4(0.f, 0.f, 0.f, 0.f);
            if (n0 + c < Nc) v = *(const float4*)(B + (size_t)(k0 + r) * Nc + n0 + c);
            *(float4*)&Bs[r][c] = v;
        }
        __syncthreads();
#pragma unroll 16
        for (int k = 0; k < 64; k++) {
            float4 bv = *(const float4*)&Bs[k][tx << 2];
            float a0 = As[(ty << 2) + 0][k];
            float a1 = As[(ty << 2) + 1][k];
            float a2 = As[(ty << 2) + 2][k];
            float a3 = As[(ty << 2) + 3][k];
            acc[0][0] += a0 * bv.x; acc[0][1] += a0 * bv.y; acc[0][2] += a0 * bv.z; acc[0][3] += a0 * bv.w;
            acc[1][0] += a1 * bv.x; acc[1][1] += a1 * bv.y; acc[1][2] += a1 * bv.z; acc[1][3] += a1 * bv.w;
            acc[2][0] += a2 * bv.x; acc[2][1] += a2 * bv.y; acc[2][2] += a2 * bv.z; acc[2][3] += a2 * bv.w;
            acc[3][0] += a3 * bv.x; acc[3][1] += a3 * bv.y; acc[3][2] += a3 * bv.z; acc[3][3] += a3 * bv.w;
        }
        __syncthreads();
    }

    int col = n0 + (tx << 2);
    if (col < Nc) {
        float b0 = 0.f, b1 = 0.f, b2 = 0.f, b3 = 0.f;
        if (bias) { b0 = bias[col]; b1 = bias[col + 1]; b2 = bias[col + 2]; b3 = bias[col + 3]; }
#pragma unroll
        for (int m = 0; m < 4; m++) {
            int gr = m0 + (ty << 2) + m;
            if (gr < M) {
                float4 o;
                o.x = acc[m][0] + b0;
                o.y = acc[m][1] + b1;
                o.z = acc[m][2] + b2;
                o.w = acc[m][3] + b3;
                if (ACT == 1) {
                    o.x = fmaxf(o.x, 0.f); o.y = fmaxf(o.y, 0.f);
                    o.z = fmaxf(o.z, 0.f); o.w = fmaxf(o.w, 0.f);
                }
                *(float4*)(C + (size_t)gr * Nc + col) = o;
            }
        }
    }
}

// ---------------- GRU elementwise ----------------
__global__ void gru_kernel(const float* __restrict__ gi, const float* __restrict__ gh,
                           const float* __restrict__ hprev, float* __restrict__ hout, int N) {
    int idx = blockIdx.x * blockDim.x + threadIdx.x;
    if (idx >= N * HDIM) return;
    int i = idx >> 7;
    int j = idx & 127;
    size_t base = (size_t)i * G3;
    float ir = gi[base + j],       hr = gh[base + j];
    float iz = gi[base + 128 + j], hz = gh[base + 128 + j];
    float in_ = gi[base + 256 + j], hn = gh[base + 256 + j];
    float r = 1.0f / (1.0f + expf(-(ir + hr)));
    float z = 1.0f / (1.0f + expf(-(iz + hz)));
    float n = tanhf(in_ + r * hn);
    hout[idx] = (1.0f - z) * n + z * hprev[idx];
}

// ---------------- edge scatter: one warp per edge, float4 vector atomics ----------------
__global__ __launch_bounds__(256) void scatter_kernel(
    const int* __restrict__ src, const int* __restrict__ dst,
    const float* __restrict__ norm, const float* __restrict__ xw,
    float* __restrict__ agg, int E)
{
    int e = (int)(((size_t)blockIdx.x * blockDim.x + threadIdx.x) >> 5);
    if (e >= E) return;
    int lane = threadIdx.x & 31;
    int s = __ldg(src + e);
    int d = __ldg(dst + e);
    float nm = __ldg(norm + e);
    float4 v = *(const float4*)(xw + (size_t)s * HDIM + (lane << 2));
    v.x *= nm; v.y *= nm; v.z *= nm; v.w *= nm;
    atomicAdd((float4*)(agg + (size_t)d * HDIM + (lane << 2)), v);
}

// ---------------- finalize GCN layer: agg + self-loop + bias, relu ----------------
__global__ void finalize_kernel(const float* __restrict__ agg, const float* __restrict__ xw,
                                const float* __restrict__ dinv, const float* __restrict__ bias,
                                float* __restrict__ xh, int N) {
    int idx = blockIdx.x * blockDim.x + threadIdx.x;
    if (idx >= N * HDIM) return;
    int i = idx >> 7;
    int j = idx & 127;
    float di = dinv[i];
    float v = agg[idx] + xw[idx] * di * di + bias[j];
    xh[idx] = fmaxf(v, 0.0f);
}

// ---------------- host launch ----------------
extern "C" void kernel_launch(void* const* d_in, const int* in_sizes, int n_in,
                              void* d_out, int out_size) {
    const float* x     = (const float*)d_in[0];
    const int*   ei    = (const int*)d_in[1];
    const float* ew    = (const float*)d_in[2];
    const float* h0    = (const float*)d_in[3];
    const float* linW  = (const float*)d_in[4];
    const float* linB  = (const float*)d_in[5];
    const float* convW = (const float*)d_in[6];   // [3,128,128]
    const float* convB = (const float*)d_in[7];   // [3,128]
    const float* Wih   = (const float*)d_in[8];   // [384,128]
    const float* Whh   = (const float*)d_in[9];   // [384,128]
    const float* bih   = (const float*)d_in[10];
    const float* bhh   = (const float*)d_in[11];
    const float* fcW   = (const float*)d_in[12];  // [128,40]
    const float* fcB   = (const float*)d_in[13];
    float* out = (float*)d_out;

    const int N = in_sizes[0] / HDIM;
    const int E = in_sizes[2];
    const int C = in_sizes[13];                  // 40
    const int* src = ei;
    const int* dst = ei + E;

    float *p_xh, *p_xw, *p_agg, *p_h, *p_gi, *p_gh, *p_deg, *p_dinv, *p_norm, *p_WihT, *p_WhhT;
    cudaGetSymbolAddress((void**)&p_xh, g_xh);
    cudaGetSymbolAddress((void**)&p_xw, g_xw);
    cudaGetSymbolAddress((void**)&p_agg, g_agg);
    cudaGetSymbolAddress((void**)&p_h, g_h);
    cudaGetSymbolAddress((void**)&p_gi, g_gi);
    cudaGetSymbolAddress((void**)&p_gh, g_gh);
    cudaGetSymbolAddress((void**)&p_deg, g_deg);
    cudaGetSymbolAddress((void**)&p_dinv, g_dinv);
    cudaGetSymbolAddress((void**)&p_norm, g_norm);
    cudaGetSymbolAddress((void**)&p_WihT, g_WihT);
    cudaGetSymbolAddress((void**)&p_WhhT, g_WhhT);

    const int T = 256;
    auto cdiv = [](int a, int b) { return (a + b - 1) / b; };

    // 1) transpose GRU weights
    transpose_g_kernel<<<cdiv(G3 * HDIM, T), T>>>(Wih, p_WihT, G3, HDIM);
    transpose_g_kernel<<<cdiv(G3 * HDIM, T), T>>>(Whh, p_WhhT, G3, HDIM);

    // 2) graph normalization (invariant across the 3 conv layers)
    init_deg_kernel<<<cdiv(N, T), T>>>(p_deg, N);
    deg_accum_kernel<<<cdiv(E, T), T>>>(dst, ew, p_deg, E);
    dinv_kernel<<<cdiv(N, T), T>>>(p_deg, p_dinv, N);
    norm_kernel<<<cdiv(E, T), T>>>(src, dst, ew, p_dinv, p_norm, E);

    // 3) xh = relu(x @ linW + linB)
    {
        dim3 g(cdiv(HDIM, 64), cdiv(N, 64));
        sgemm_k128<1><<<g, 256>>>(x, linW, linB, p_xh, N, HDIM);
    }

    // 4) first GRU: h = GRU(xh, h0)
    {
        dim3 g(cdiv(G3, 64), cdiv(N, 64));
        sgemm_k128<0><<<g, 256>>>(p_xh, p_WihT, bih, p_gi, N, G3);
        sgemm_k128<0><<<g, 256>>>(h0, p_WhhT, bhh, p_gh, N, G3);
        gru_kernel<<<cdiv(N * HDIM, T), T>>>(p_gi, p_gh, h0, p_h, N);
    }

    // 5) 3 GCN layers + GRU
    for (int l = 0; l < 3; l++) {
        dim3 gc(cdiv(HDIM, 64), cdiv(N, 64));
        sgemm_k128<0><<<gc, 256>>>(p_xh, convW + (size_t)l * HDIM * HDIM, nullptr, p_xw, N, HDIM);
        zero_kernel<<<2048, 256>>>(p_agg, (size_t)N * HDIM);
        scatter_kernel<<<(int)(((size_t)E * 32 + 255) / 256), 256>>>(src, dst, p_norm, p_xw, p_agg, E);
        finalize_kernel<<<cdiv(N * HDIM, T), T>>>(p_agg, p_xw, p_dinv, convB + (size_t)l * HDIM, p_xh, N);

        dim3 gg(cdiv(G3, 64), cdiv(N, 64));
        sgemm_k128<0><<<gg, 256>>>(p_xh, p_WihT, bih, p_gi, N, G3);
        sgemm_k128<0><<<gg, 256>>>(p_h, p_WhhT, bhh, p_gh, N, G3);
        gru_kernel<<<cdiv(N * HDIM, T), T>>>(p_gi, p_gh, p_h, p_h, N);
    }

    // 6) out = h @ fcW + fcB
    {
        dim3 g(cdiv(C, 64), cdiv(N, 64));
        sgemm_k128<0><<<g, 256>>>(p_h, fcW, fcB, out, N, C);
    }
}